// round 7
// baseline (speedup 1.0000x reference)
#include <cuda_runtime.h>
#include <math.h>

#define BN   4
#define SEQ  1024
#define CH   768
#define NH   12
#define HD   64
#define ROWS (BN*SEQ)
#define QKVC (3*CH)
#define BH   (BN*NH)
#define BETA 0.2f
#define SCALE 0.125f
#define LN_EPS 1e-5f

__device__ float g_xn[(size_t)ROWS * CH];
__device__ float g_qkv[(size_t)ROWS * QKVC];
__device__ float g_S[(size_t)BH * SEQ * SEQ];
__device__ float g_P[(size_t)BH * SEQ * SEQ];

__device__ __forceinline__ float to_tf32(float x) {
    unsigned u;
    asm("cvt.rna.tf32.f32 %0, %1;" : "=r"(u) : "f"(x));
    return __uint_as_float(u);
}
__device__ __forceinline__ void mma8(float* c, const float* a, const float* b) {
    asm volatile(
        "mma.sync.aligned.m16n8k8.row.col.f32.tf32.tf32.f32 "
        "{%0,%1,%2,%3}, {%4,%5,%6,%7}, {%8,%9}, {%0,%1,%2,%3};"
        : "+f"(c[0]), "+f"(c[1]), "+f"(c[2]), "+f"(c[3])
        : "r"(__float_as_uint(a[0])), "r"(__float_as_uint(a[1])),
          "r"(__float_as_uint(a[2])), "r"(__float_as_uint(a[3])),
          "r"(__float_as_uint(b[0])), "r"(__float_as_uint(b[1])));
}

/* ================= LayerNorm: one block per token ================= */
__global__ void ln_kernel(const float* __restrict__ x,
                          const float* __restrict__ gamma,
                          const float* __restrict__ beta) {
    int row = blockIdx.x;
    const float* xr = x + (size_t)row * CH;
    float*       orow = g_xn + (size_t)row * CH;
    int t = threadIdx.x;

    float v0 = xr[t], v1 = xr[t + 256], v2 = xr[t + 512];
    float s  = v0 + v1 + v2;
    float sq = v0 * v0 + v1 * v1 + v2 * v2;

    __shared__ float redS[8], redQ[8], stats[2];
    #pragma unroll
    for (int o = 16; o; o >>= 1) {
        s  += __shfl_down_sync(0xffffffffu, s,  o);
        sq += __shfl_down_sync(0xffffffffu, sq, o);
    }
    int w = t >> 5, l = t & 31;
    if (l == 0) { redS[w] = s; redQ[w] = sq; }
    __syncthreads();
    if (t == 0) {
        float S = 0.f, Q = 0.f;
        #pragma unroll
        for (int i = 0; i < 8; i++) { S += redS[i]; Q += redQ[i]; }
        float mu  = S * (1.0f / CH);
        float var = Q * (1.0f / CH) - mu * mu;
        stats[0] = mu;
        stats[1] = rsqrtf(var + LN_EPS);
    }
    __syncthreads();
    float mu = stats[0], rs = stats[1];
    orow[t]       = (v0 - mu) * rs * gamma[t]       + beta[t];
    orow[t + 256] = (v1 - mu) * rs * gamma[t + 256] + beta[t + 256];
    orow[t + 512] = (v2 - mu) * rs * gamma[t + 512] + beta[t + 512];
}

/* ===== macro: one 128x64 MMA compute step from staged smem buffers ===== */
#define COMPUTE_TILE(AS, BS)                                              \
    _Pragma("unroll")                                                     \
    for (int kc = 0; kc < 2; kc++) {                                      \
        int kb = kc * 8;                                                  \
        float a[2][4], bfr[4][2];                                         \
        _Pragma("unroll")                                                 \
        for (int mi = 0; mi < 2; mi++) {                                  \
            a[mi][0] = AS[wm + mi*16 + lr    ][kb + lc];                  \
            a[mi][1] = AS[wm + mi*16 + lr + 8][kb + lc];                  \
            a[mi][2] = AS[wm + mi*16 + lr    ][kb + lc + 4];              \
            a[mi][3] = AS[wm + mi*16 + lr + 8][kb + lc + 4];              \
        }                                                                 \
        _Pragma("unroll")                                                 \
        for (int ni = 0; ni < 4; ni++) {                                  \
            bfr[ni][0] = BS[wn + ni*8 + lr][kb + lc];                     \
            bfr[ni][1] = BS[wn + ni*8 + lr][kb + lc + 4];                 \
        }                                                                 \
        _Pragma("unroll")                                                 \
        for (int mi = 0; mi < 2; mi++)                                    \
            _Pragma("unroll")                                             \
            for (int ni = 0; ni < 4; ni++)                                \
                mma8(acc[mi][ni], a[mi], bfr[ni]);                        \
    }

#define STORE_AB(AS, BS, va0, va1, vb)                                    \
    AS[r][c4+0]=to_tf32(va0.x); AS[r][c4+1]=to_tf32(va0.y);               \
    AS[r][c4+2]=to_tf32(va0.z); AS[r][c4+3]=to_tf32(va0.w);               \
    AS[r+64][c4+0]=to_tf32(va1.x); AS[r+64][c4+1]=to_tf32(va1.y);         \
    AS[r+64][c4+2]=to_tf32(va1.z); AS[r+64][c4+3]=to_tf32(va1.w);         \
    BS[r][c4+0]=to_tf32(vb.x); BS[r][c4+1]=to_tf32(vb.y);                 \
    BS[r][c4+2]=to_tf32(vb.z); BS[r][c4+3]=to_tf32(vb.w);

/* ========== QKV GEMM (tf32 MMA, double-buffered) ========== */
__global__ __launch_bounds__(256) void qkv_gemm(const float* __restrict__ W,
                                                const float* __restrict__ bias) {
    __shared__ float As[2][128][20];
    __shared__ float Bs[2][64][20];
    int m0 = blockIdx.y * 128, n0 = blockIdx.x * 64;
    int t = threadIdx.x;
    int warp = t >> 5, lane = t & 31, lr = lane >> 2, lc = lane & 3;
    int wm = (warp >> 1) * 32, wn = (warp & 1) * 32;
    int r = t >> 2, c4 = (t & 3) * 4;

    const float* A0 = g_xn + (size_t)(m0 + r) * CH;
    const float* A1 = g_xn + (size_t)(m0 + r + 64) * CH;
    const float* B0 = W    + (size_t)(n0 + r) * CH;

    float acc[2][4][4] = {};
    {
        float4 a0 = *(const float4*)(A0 + c4);
        float4 a1 = *(const float4*)(A1 + c4);
        float4 bb = *(const float4*)(B0 + c4);
        STORE_AB(As[0], Bs[0], a0, a1, bb)
    }
    __syncthreads();

    const int NT = CH / 16;
    int buf = 0;
    for (int kt = 0; kt < NT; kt++) {
        float4 na0, na1, nbb;
        bool nxt = (kt + 1) < NT;
        if (nxt) {
            int k0 = (kt + 1) * 16;
            na0 = *(const float4*)(A0 + k0 + c4);
            na1 = *(const float4*)(A1 + k0 + c4);
            nbb = *(const float4*)(B0 + k0 + c4);
        }
        COMPUTE_TILE(As[buf], Bs[buf])
        if (nxt) {
            int nb = buf ^ 1;
            STORE_AB(As[nb], Bs[nb], na0, na1, nbb)
        }
        __syncthreads();
        buf ^= 1;
    }
    #pragma unroll
    for (int mi = 0; mi < 2; mi++)
        #pragma unroll
        for (int ni = 0; ni < 4; ni++) {
            int row = m0 + wm + mi*16 + lr;
            int col = n0 + wn + ni*8 + lc*2;
            g_qkv[(size_t)row * QKVC + col    ] = acc[mi][ni][0] + bias[col];
            g_qkv[(size_t)row * QKVC + col + 1] = acc[mi][ni][1] + bias[col+1];
            g_qkv[(size_t)(row+8) * QKVC + col    ] = acc[mi][ni][2] + bias[col];
            g_qkv[(size_t)(row+8) * QKVC + col + 1] = acc[mi][ni][3] + bias[col+1];
        }
}

/* ========== Scores (tf32 MMA, double-buffered) ========== */
__global__ __launch_bounds__(256) void score_gemm() {
    int bh = blockIdx.z, b = bh / NH, h = bh % NH;
    const float* Q = g_qkv + (size_t)b * SEQ * QKVC + h * HD;
    const float* K = g_qkv + (size_t)b * SEQ * QKVC + CH + h * HD;
    float* S = g_S + (size_t)bh * SEQ * SEQ;

    __shared__ float As[2][128][20];
    __shared__ float Bs[2][64][20];
    int m0 = blockIdx.y * 128, n0 = blockIdx.x * 64;
    int t = threadIdx.x;
    int warp = t >> 5, lane = t & 31, lr = lane >> 2, lc = lane & 3;
    int wm = (warp >> 1) * 32, wn = (warp & 1) * 32;
    int r = t >> 2, c4 = (t & 3) * 4;

    const float* A0 = Q + (size_t)(m0 + r) * QKVC;
    const float* A1 = Q + (size_t)(m0 + r + 64) * QKVC;
    const float* B0 = K + (size_t)(n0 + r) * QKVC;

    float acc[2][4][4] = {};
    {
        float4 a0 = *(const float4*)(A0 + c4);
        float4 a1 = *(const float4*)(A1 + c4);
        float4 bb = *(const float4*)(B0 + c4);
        STORE_AB(As[0], Bs[0], a0, a1, bb)
    }
    __syncthreads();

    const int NT = HD / 16;
    int buf = 0;
    for (int kt = 0; kt < NT; kt++) {
        float4 na0, na1, nbb;
        bool nxt = (kt + 1) < NT;
        if (nxt) {
            int k0 = (kt + 1) * 16;
            na0 = *(const float4*)(A0 + k0 + c4);
            na1 = *(const float4*)(A1 + k0 + c4);
            nbb = *(const float4*)(B0 + k0 + c4);
        }
        COMPUTE_TILE(As[buf], Bs[buf])
        if (nxt) {
            int nb = buf ^ 1;
            STORE_AB(As[nb], Bs[nb], na0, na1, nbb)
        }
        __syncthreads();
        buf ^= 1;
    }
    #pragma unroll
    for (int mi = 0; mi < 2; mi++)
        #pragma unroll
        for (int ni = 0; ni < 4; ni++) {
            int row = m0 + wm + mi*16 + lr;
            int col = n0 + wn + ni*8 + lc*2;
            S[(size_t)row * SEQ + col    ] = acc[mi][ni][0] * SCALE;
            S[(size_t)row * SEQ + col + 1] = acc[mi][ni][1] * SCALE;
            S[(size_t)(row+8) * SEQ + col    ] = acc[mi][ni][2] * SCALE;
            S[(size_t)(row+8) * SEQ + col + 1] = acc[mi][ni][3] * SCALE;
        }
}

/* ============ Lateral inhibition conv + row softmax (v2) ============ */
#define CR 4
__global__ __launch_bounds__(256) void conv_softmax_v2() {
    int bh = blockIdx.y;
    int i0 = blockIdx.x * CR;
    const float* S = g_S + (size_t)bh * SEQ * SEQ;
    float*       P = g_P + (size_t)bh * SEQ * SEQ;

    __shared__ float rows[6][SEQ];
    __shared__ float red[CR][8];
    __shared__ float bc[CR];

    int t = threadIdx.x, lane = t & 31, w = t >> 5;
    int j0 = t * 4;

    #pragma unroll
    for (int r = 0; r < 6; r++) {
        int gi = i0 - 1 + r;
        float4 v = make_float4(0.f, 0.f, 0.f, 0.f);
        if (gi >= 0 && gi < SEQ) v = *(const float4*)(S + (size_t)gi * SEQ + j0);
        *(float4*)&rows[r][j0] = v;
    }
    __syncthreads();

    float a[CR][4], mx[CR];
    #pragma unroll
    for (int r = 0; r < CR; r++) {
        float4 x = *(const float4*)&rows[r    ][j0];
        float4 y = *(const float4*)&rows[r + 1][j0];
        float4 z = *(const float4*)&rows[r + 2][j0];
        float4 vs;
        vs.x = x.x + y.x + z.x;  vs.y = x.y + y.y + z.y;
        vs.z = x.z + y.z + z.z;  vs.w = x.w + y.w + z.w;

        float left  = __shfl_up_sync(0xffffffffu, vs.w, 1);
        float right = __shfl_down_sync(0xffffffffu, vs.x, 1);
        if (lane == 0) {
            int j = j0 - 1;
            left = (j >= 0) ? rows[r][j] + rows[r + 1][j] + rows[r + 2][j] : 0.f;
        }
        if (lane == 31) {
            int j = j0 + 4;
            right = (j < SEQ) ? rows[r][j] + rows[r + 1][j] + rows[r + 2][j] : 0.f;
        }

        a[r][0] = (1.0f + BETA) * y.x - BETA * (left + vs.x + vs.y);
        a[r][1] = (1.0f + BETA) * y.y - BETA * (vs.x + vs.y + vs.z);
        a[r][2] = (1.0f + BETA) * y.z - BETA * (vs.y + vs.z + vs.w);
        a[r][3] = (1.0f + BETA) * y.w - BETA * (vs.z + vs.w + right);
        mx[r] = fmaxf(fmaxf(a[r][0], a[r][1]), fmaxf(a[r][2], a[r][3]));
    }

    #pragma unroll
    for (int r = 0; r < CR; r++) {
        float m = mx[r];
        #pragma unroll
        for (int o = 16; o; o >>= 1) m = fmaxf(m, __shfl_xor_sync(0xffffffffu, m, o));
        if (lane == 0) red[r][w] = m;
    }
    __syncthreads();
    if (t < CR) {
        float m = red[t][0];
        #pragma unroll
        for (int k = 1; k < 8; k++) m = fmaxf(m, red[t][k]);
        bc[t] = m;
    }
    __syncthreads();

    float sm[CR];
    #pragma unroll
    for (int r = 0; r < CR; r++) {
        float M = bc[r];
        float s = 0.f;
        #pragma unroll
        for (int q = 0; q < 4; q++) { a[r][q] = __expf(a[r][q] - M); s += a[r][q]; }
        sm[r] = s;
    }
    __syncthreads();
    #pragma unroll
    for (int r = 0; r < CR; r++) {
        float s = sm[r];
        #pragma unroll
        for (int o = 16; o; o >>= 1) s += __shfl_xor_sync(0xffffffffu, s, o);
        if (lane == 0) red[r][w] = s;
    }
    __syncthreads();
    if (t < CR) {
        float s = 0.f;
        #pragma unroll
        for (int k = 0; k < 8; k++) s += red[t][k];
        bc[t] = 1.0f / s;
    }
    __syncthreads();

    #pragma unroll
    for (int r = 0; r < CR; r++) {
        float inv = bc[r];
        float4 o;
        o.x = a[r][0] * inv; o.y = a[r][1] * inv;
        o.z = a[r][2] * inv; o.w = a[r][3] * inv;
        *(float4*)(P + (size_t)(i0 + r) * SEQ + j0) = o;
    }
}

/* ========== PV GEMM (tf32 MMA, double-buffered) ========== */
__global__ __launch_bounds__(256) void pv_gemm(float* __restrict__ out) {
    int bh = blockIdx.y, b = bh / NH, h = bh % NH;
    const float* P = g_P + (size_t)bh * SEQ * SEQ;
    const float* V = g_qkv + (size_t)b * SEQ * QKVC + 2 * CH + h * HD;
    int m0 = blockIdx.x * 128;

    __shared__ float As[2][128][20];
    __shared__ float Vs[2][16][72];
    int t = threadIdx.x;
    int warp = t >> 5, lane = t & 31, lr = lane >> 2, lc = lane & 3;
    int wm = (warp >> 1) * 32, wn = (warp & 1) * 32;
    int r = t >> 2, c4 = (t & 3) * 4;
    int kr = t >> 4, vc4 = (t & 15) * 4;

    const float* A0 = P + (size_t)(m0 + r) * SEQ;
    const float* A1 = P + (size_t)(m0 + r + 64) * SEQ;

    float acc[2][4][4] = {};
    {
        float4 a0 = *(const float4*)(A0 + c4);
        float4 a1 = *(const float4*)(A1 + c4);
        float4 v  = *(const float4*)(V + (size_t)kr * QKVC + vc4);
        As[0][r][c4+0]=to_tf32(a0.x); As[0][r][c4+1]=to_tf32(a0.y);
        As[0][r][c4+2]=to_tf32(a0.z); As[0][r][c4+3]=to_tf32(a0.w);
        As[0][r+64][c4+0]=to_tf32(a1.x); As[0][r+64][c4+1]=to_tf32(a1.y);
        As[0][r+64][c4+2]=to_tf32(a1.z); As[0][r+64][c4+3]=to_tf32(a1.w);
        Vs[0][kr][vc4+0]=to_tf32(v.x); Vs[0][kr][vc4+1]=to_tf32(v.y);
        Vs[0][kr][vc4+2]=to_tf32(v.z); Vs[0][kr][vc4+3]=to_tf32(v.w);
    }
    __syncthreads();

    const int NT = SEQ / 16;
    int buf = 0;
    for (int kt = 0; kt < NT; kt++) {
        float4 na0, na1, nv;
        bool nxt = (kt + 1) < NT;
        if (nxt) {
            int k0 = (kt + 1) * 16;
            na0 = *(const float4*)(A0 + k0 + c4);
            na1 = *(const float4*)(A1 + k0 + c4);
            nv  = *(const float4*)(V + (size_t)(k0 + kr) * QKVC + vc4);
        }
        /* compute */
        #pragma unroll
        for (int kc = 0; kc < 2; kc++) {
            int kb = kc * 8;
            float a[2][4], bfr[4][2];
            #pragma unroll
            for (int mi = 0; mi < 2; mi++) {
                a[mi][0] = As[buf][wm + mi*16 + lr    ][kb + lc];
                a[mi][1] = As[buf][wm + mi*16 + lr + 8][kb + lc];
                a[mi][2] = As[buf][wm + mi*16 + lr    ][kb + lc + 4];
                a[mi][3] = As[buf][wm + mi*16 + lr + 8][kb + lc + 4];
            }
            #pragma unroll
            for (int ni = 0; ni < 4; ni++) {
                bfr[ni][0] = Vs[buf][kb + lc    ][wn + ni*8 + lr];
                bfr[ni][1] = Vs[buf][kb + lc + 4][wn + ni*8 + lr];
            }
            #pragma unroll
            for (int mi = 0; mi < 2; mi++)
                #pragma unroll
                for (int ni = 0; ni < 4; ni++)
                    mma8(acc[mi][ni], a[mi], bfr[ni]);
        }
        if (nxt) {
            int nb = buf ^ 1;
            As[nb][r][c4+0]=to_tf32(na0.x); As[nb][r][c4+1]=to_tf32(na0.y);
            As[nb][r][c4+2]=to_tf32(na0.z); As[nb][r][c4+3]=to_tf32(na0.w);
            As[nb][r+64][c4+0]=to_tf32(na1.x); As[nb][r+64][c4+1]=to_tf32(na1.y);
            As[nb][r+64][c4+2]=to_tf32(na1.z); As[nb][r+64][c4+3]=to_tf32(na1.w);
            Vs[nb][kr][vc4+0]=to_tf32(nv.x); Vs[nb][kr][vc4+1]=to_tf32(nv.y);
            Vs[nb][kr][vc4+2]=to_tf32(nv.z); Vs[nb][kr][vc4+3]=to_tf32(nv.w);
        }
        __syncthreads();
        buf ^= 1;
    }
    #pragma unroll
    for (int mi = 0; mi < 2; mi++)
        #pragma unroll
        for (int ni = 0; ni < 4; ni++) {
            int row = m0 + wm + mi*16 + lr;
            int col = wn + ni*8 + lc*2;
            out[((size_t)b * SEQ + row) * CH + h*HD + col    ] = acc[mi][ni][0];
            out[((size_t)b * SEQ + row) * CH + h*HD + col + 1] = acc[mi][ni][1];
            out[((size_t)b * SEQ + row + 8) * CH + h*HD + col    ] = acc[mi][ni][2];
            out[((size_t)b * SEQ + row + 8) * CH + h*HD + col + 1] = acc[mi][ni][3];
        }
}

extern "C" void kernel_launch(void* const* d_in, const int* in_sizes, int n_in,
                              void* d_out, int out_size) {
    const float* x     = (const float*)d_in[0];
    const float* qkv_w = (const float*)d_in[1];
    const float* qkv_b = (const float*)d_in[2];
    const float* ln_g  = (const float*)d_in[3];
    const float* ln_b  = (const float*)d_in[4];
    float* out = (float*)d_out;

    ln_kernel<<<ROWS, 256>>>(x, ln_g, ln_b);
    qkv_gemm<<<dim3(QKVC / 64, ROWS / 128), 256>>>(qkv_w, qkv_b);
    score_gemm<<<dim3(SEQ / 64, SEQ / 128, BH), 256>>>();
    conv_softmax_v2<<<dim3(SEQ / CR, BH), 256>>>();
    pv_gemm<<<dim3(SEQ / 128, BH), 256>>>(out);
}

// round 8
// speedup vs baseline: 1.0035x; 1.0035x over previous
#include <cuda_runtime.h>
#include <math.h>

#define BN   4
#define SEQ  1024
#define CH   768
#define NH   12
#define HD   64
#define ROWS (BN*SEQ)
#define QKVC (3*CH)
#define BH   (BN*NH)
#define BETA 0.2f
#define SCALE 0.125f
#define LN_EPS 1e-5f

__device__ float g_xn[(size_t)ROWS * CH];
__device__ float g_qkv[(size_t)ROWS * QKVC];
__device__ float g_S[(size_t)BH * SEQ * SEQ];
__device__ float g_P[(size_t)BH * SEQ * SEQ];

__device__ __forceinline__ float to_tf32(float x) {
    unsigned u;
    asm("cvt.rna.tf32.f32 %0, %1;" : "=r"(u) : "f"(x));
    return __uint_as_float(u);
}
__device__ __forceinline__ void mma8(float* c, const float* a, const float* b) {
    asm volatile(
        "mma.sync.aligned.m16n8k8.row.col.f32.tf32.tf32.f32 "
        "{%0,%1,%2,%3}, {%4,%5,%6,%7}, {%8,%9}, {%0,%1,%2,%3};"
        : "+f"(c[0]), "+f"(c[1]), "+f"(c[2]), "+f"(c[3])
        : "r"(__float_as_uint(a[0])), "r"(__float_as_uint(a[1])),
          "r"(__float_as_uint(a[2])), "r"(__float_as_uint(a[3])),
          "r"(__float_as_uint(b[0])), "r"(__float_as_uint(b[1])));
}

/* ================= LayerNorm: one block per token ================= */
__global__ void ln_kernel(const float* __restrict__ x,
                          const float* __restrict__ gamma,
                          const float* __restrict__ beta) {
    int row = blockIdx.x;
    const float* xr = x + (size_t)row * CH;
    float*       orow = g_xn + (size_t)row * CH;
    int t = threadIdx.x;

    float v0 = xr[t], v1 = xr[t + 256], v2 = xr[t + 512];
    float s  = v0 + v1 + v2;
    float sq = v0 * v0 + v1 * v1 + v2 * v2;

    __shared__ float redS[8], redQ[8], stats[2];
    #pragma unroll
    for (int o = 16; o; o >>= 1) {
        s  += __shfl_down_sync(0xffffffffu, s,  o);
        sq += __shfl_down_sync(0xffffffffu, sq, o);
    }
    int w = t >> 5, l = t & 31;
    if (l == 0) { redS[w] = s; redQ[w] = sq; }
    __syncthreads();
    if (t == 0) {
        float S = 0.f, Q = 0.f;
        #pragma unroll
        for (int i = 0; i < 8; i++) { S += redS[i]; Q += redQ[i]; }
        float mu  = S * (1.0f / CH);
        float var = Q * (1.0f / CH) - mu * mu;
        stats[0] = mu;
        stats[1] = rsqrtf(var + LN_EPS);
    }
    __syncthreads();
    float mu = stats[0], rs = stats[1];
    orow[t]       = (v0 - mu) * rs * gamma[t]       + beta[t];
    orow[t + 256] = (v1 - mu) * rs * gamma[t + 256] + beta[t + 256];
    orow[t + 512] = (v2 - mu) * rs * gamma[t + 512] + beta[t + 512];
}

/* ===== macro: one 128x64 MMA compute step from staged smem buffers ===== */
#define COMPUTE_TILE(AS, BS)                                              \
    _Pragma("unroll")                                                     \
    for (int kc = 0; kc < 2; kc++) {                                      \
        int kb = kc * 8;                                                  \
        float a[2][4], bfr[4][2];                                         \
        _Pragma("unroll")                                                 \
        for (int mi = 0; mi < 2; mi++) {                                  \
            a[mi][0] = AS[wm + mi*16 + lr    ][kb + lc];                  \
            a[mi][1] = AS[wm + mi*16 + lr + 8][kb + lc];                  \
            a[mi][2] = AS[wm + mi*16 + lr    ][kb + lc + 4];              \
            a[mi][3] = AS[wm + mi*16 + lr + 8][kb + lc + 4];              \
        }                                                                 \
        _Pragma("unroll")                                                 \
        for (int ni = 0; ni < 4; ni++) {                                  \
            bfr[ni][0] = BS[wn + ni*8 + lr][kb + lc];                     \
            bfr[ni][1] = BS[wn + ni*8 + lr][kb + lc + 4];                 \
        }                                                                 \
        _Pragma("unroll")                                                 \
        for (int mi = 0; mi < 2; mi++)                                    \
            _Pragma("unroll")                                             \
            for (int ni = 0; ni < 4; ni++)                                \
                mma8(acc[mi][ni], a[mi], bfr[ni]);                        \
    }

#define STORE_AB(AS, BS, va0, va1, vb)                                    \
    AS[r][c4+0]=to_tf32(va0.x); AS[r][c4+1]=to_tf32(va0.y);               \
    AS[r][c4+2]=to_tf32(va0.z); AS[r][c4+3]=to_tf32(va0.w);               \
    AS[r+64][c4+0]=to_tf32(va1.x); AS[r+64][c4+1]=to_tf32(va1.y);         \
    AS[r+64][c4+2]=to_tf32(va1.z); AS[r+64][c4+3]=to_tf32(va1.w);         \
    BS[r][c4+0]=to_tf32(vb.x); BS[r][c4+1]=to_tf32(vb.y);                 \
    BS[r][c4+2]=to_tf32(vb.z); BS[r][c4+3]=to_tf32(vb.w);

/* ========== QKV GEMM (tf32 MMA, double-buffered) ========== */
__global__ __launch_bounds__(256) void qkv_gemm(const float* __restrict__ W,
                                                const float* __restrict__ bias) {
    __shared__ float As[2][128][20];
    __shared__ float Bs[2][64][20];
    int m0 = blockIdx.y * 128, n0 = blockIdx.x * 64;
    int t = threadIdx.x;
    int warp = t >> 5, lane = t & 31, lr = lane >> 2, lc = lane & 3;
    int wm = (warp >> 1) * 32, wn = (warp & 1) * 32;
    int r = t >> 2, c4 = (t & 3) * 4;

    const float* A0 = g_xn + (size_t)(m0 + r) * CH;
    const float* A1 = g_xn + (size_t)(m0 + r + 64) * CH;
    const float* B0 = W    + (size_t)(n0 + r) * CH;

    float acc[2][4][4] = {};
    {
        float4 a0 = *(const float4*)(A0 + c4);
        float4 a1 = *(const float4*)(A1 + c4);
        float4 bb = *(const float4*)(B0 + c4);
        STORE_AB(As[0], Bs[0], a0, a1, bb)
    }
    __syncthreads();

    const int NT = CH / 16;
    int buf = 0;
    for (int kt = 0; kt < NT; kt++) {
        float4 na0, na1, nbb;
        bool nxt = (kt + 1) < NT;
        if (nxt) {
            int k0 = (kt + 1) * 16;
            na0 = *(const float4*)(A0 + k0 + c4);
            na1 = *(const float4*)(A1 + k0 + c4);
            nbb = *(const float4*)(B0 + k0 + c4);
        }
        COMPUTE_TILE(As[buf], Bs[buf])
        if (nxt) {
            int nb = buf ^ 1;
            STORE_AB(As[nb], Bs[nb], na0, na1, nbb)
        }
        __syncthreads();
        buf ^= 1;
    }
    #pragma unroll
    for (int mi = 0; mi < 2; mi++)
        #pragma unroll
        for (int ni = 0; ni < 4; ni++) {
            int row = m0 + wm + mi*16 + lr;
            int col = n0 + wn + ni*8 + lc*2;
            g_qkv[(size_t)row * QKVC + col    ] = acc[mi][ni][0] + bias[col];
            g_qkv[(size_t)row * QKVC + col + 1] = acc[mi][ni][1] + bias[col+1];
            g_qkv[(size_t)(row+8) * QKVC + col    ] = acc[mi][ni][2] + bias[col];
            g_qkv[(size_t)(row+8) * QKVC + col + 1] = acc[mi][ni][3] + bias[col+1];
        }
}

/* ========== Scores (tf32 MMA, double-buffered) ========== */
__global__ __launch_bounds__(256) void score_gemm() {
    int bh = blockIdx.z, b = bh / NH, h = bh % NH;
    const float* Q = g_qkv + (size_t)b * SEQ * QKVC + h * HD;
    const float* K = g_qkv + (size_t)b * SEQ * QKVC + CH + h * HD;
    float* S = g_S + (size_t)bh * SEQ * SEQ;

    __shared__ float As[2][128][20];
    __shared__ float Bs[2][64][20];
    int m0 = blockIdx.y * 128, n0 = blockIdx.x * 64;
    int t = threadIdx.x;
    int warp = t >> 5, lane = t & 31, lr = lane >> 2, lc = lane & 3;
    int wm = (warp >> 1) * 32, wn = (warp & 1) * 32;
    int r = t >> 2, c4 = (t & 3) * 4;

    const float* A0 = Q + (size_t)(m0 + r) * QKVC;
    const float* A1 = Q + (size_t)(m0 + r + 64) * QKVC;
    const float* B0 = K + (size_t)(n0 + r) * QKVC;

    float acc[2][4][4] = {};
    {
        float4 a0 = *(const float4*)(A0 + c4);
        float4 a1 = *(const float4*)(A1 + c4);
        float4 bb = *(const float4*)(B0 + c4);
        STORE_AB(As[0], Bs[0], a0, a1, bb)
    }
    __syncthreads();

    const int NT = HD / 16;
    int buf = 0;
    for (int kt = 0; kt < NT; kt++) {
        float4 na0, na1, nbb;
        bool nxt = (kt + 1) < NT;
        if (nxt) {
            int k0 = (kt + 1) * 16;
            na0 = *(const float4*)(A0 + k0 + c4);
            na1 = *(const float4*)(A1 + k0 + c4);
            nbb = *(const float4*)(B0 + k0 + c4);
        }
        COMPUTE_TILE(As[buf], Bs[buf])
        if (nxt) {
            int nb = buf ^ 1;
            STORE_AB(As[nb], Bs[nb], na0, na1, nbb)
        }
        __syncthreads();
        buf ^= 1;
    }
    #pragma unroll
    for (int mi = 0; mi < 2; mi++)
        #pragma unroll
        for (int ni = 0; ni < 4; ni++) {
            int row = m0 + wm + mi*16 + lr;
            int col = n0 + wn + ni*8 + lc*2;
            S[(size_t)row * SEQ + col    ] = acc[mi][ni][0] * SCALE;
            S[(size_t)row * SEQ + col + 1] = acc[mi][ni][1] * SCALE;
            S[(size_t)(row+8) * SEQ + col    ] = acc[mi][ni][2] * SCALE;
            S[(size_t)(row+8) * SEQ + col + 1] = acc[mi][ni][3] * SCALE;
        }
}

/* ============ Lateral inhibition conv + row softmax (v2) ============ */
#define CR 4
__global__ __launch_bounds__(256) void conv_softmax_v2() {
    int bh = blockIdx.y;
    int i0 = blockIdx.x * CR;
    const float* S = g_S + (size_t)bh * SEQ * SEQ;
    float*       P = g_P + (size_t)bh * SEQ * SEQ;

    __shared__ float rows[6][SEQ];
    __shared__ float red[CR][8];
    __shared__ float bc[CR];

    int t = threadIdx.x, lane = t & 31, w = t >> 5;
    int j0 = t * 4;

    #pragma unroll
    for (int r = 0; r < 6; r++) {
        int gi = i0 - 1 + r;
        float4 v = make_float4(0.f, 0.f, 0.f, 0.f);
        if (gi >= 0 && gi < SEQ) v = *(const float4*)(S + (size_t)gi * SEQ + j0);
        *(float4*)&rows[r][j0] = v;
    }
    __syncthreads();

    float a[CR][4], mx[CR];
    #pragma unroll
    for (int r = 0; r < CR; r++) {
        float4 x = *(const float4*)&rows[r    ][j0];
        float4 y = *(const float4*)&rows[r + 1][j0];
        float4 z = *(const float4*)&rows[r + 2][j0];
        float4 vs;
        vs.x = x.x + y.x + z.x;  vs.y = x.y + y.y + z.y;
        vs.z = x.z + y.z + z.z;  vs.w = x.w + y.w + z.w;

        float left  = __shfl_up_sync(0xffffffffu, vs.w, 1);
        float right = __shfl_down_sync(0xffffffffu, vs.x, 1);
        if (lane == 0) {
            int j = j0 - 1;
            left = (j >= 0) ? rows[r][j] + rows[r + 1][j] + rows[r + 2][j] : 0.f;
        }
        if (lane == 31) {
            int j = j0 + 4;
            right = (j < SEQ) ? rows[r][j] + rows[r + 1][j] + rows[r + 2][j] : 0.f;
        }

        a[r][0] = (1.0f + BETA) * y.x - BETA * (left + vs.x + vs.y);
        a[r][1] = (1.0f + BETA) * y.y - BETA * (vs.x + vs.y + vs.z);
        a[r][2] = (1.0f + BETA) * y.z - BETA * (vs.y + vs.z + vs.w);
        a[r][3] = (1.0f + BETA) * y.w - BETA * (vs.z + vs.w + right);
        mx[r] = fmaxf(fmaxf(a[r][0], a[r][1]), fmaxf(a[r][2], a[r][3]));
    }

    #pragma unroll
    for (int r = 0; r < CR; r++) {
        float m = mx[r];
        #pragma unroll
        for (int o = 16; o; o >>= 1) m = fmaxf(m, __shfl_xor_sync(0xffffffffu, m, o));
        if (lane == 0) red[r][w] = m;
    }
    __syncthreads();
    if (t < CR) {
        float m = red[t][0];
        #pragma unroll
        for (int k = 1; k < 8; k++) m = fmaxf(m, red[t][k]);
        bc[t] = m;
    }
    __syncthreads();

    float sm[CR];
    #pragma unroll
    for (int r = 0; r < CR; r++) {
        float M = bc[r];
        float s = 0.f;
        #pragma unroll
        for (int q = 0; q < 4; q++) { a[r][q] = __expf(a[r][q] - M); s += a[r][q]; }
        sm[r] = s;
    }
    __syncthreads();
    #pragma unroll
    for (int r = 0; r < CR; r++) {
        float s = sm[r];
        #pragma unroll
        for (int o = 16; o; o >>= 1) s += __shfl_xor_sync(0xffffffffu, s, o);
        if (lane == 0) red[r][w] = s;
    }
    __syncthreads();
    if (t < CR) {
        float s = 0.f;
        #pragma unroll
        for (int k = 0; k < 8; k++) s += red[t][k];
        bc[t] = 1.0f / s;
    }
    __syncthreads();

    #pragma unroll
    for (int r = 0; r < CR; r++) {
        float inv = bc[r];
        float4 o;
        o.x = a[r][0] * inv; o.y = a[r][1] * inv;
        o.z = a[r][2] * inv; o.w = a[r][3] * inv;
        *(float4*)(P + (size_t)(i0 + r) * SEQ + j0) = o;
    }
}

/* ========== PV GEMM (tf32 MMA, double-buffered) ========== */
__global__ __launch_bounds__(256) void pv_gemm(float* __restrict__ out) {
    int bh = blockIdx.y, b = bh / NH, h = bh % NH;
    const float* P = g_P + (size_t)bh * SEQ * SEQ;
    const float* V = g_qkv + (size_t)b * SEQ * QKVC + 2 * CH + h * HD;
    int m0 = blockIdx.x * 128;

    __shared__ float As[2][128][20];
    __shared__ float Vs[2][16][72];
    int t = threadIdx.x;
    int warp = t >> 5, lane = t & 31, lr = lane >> 2, lc = lane & 3;
    int wm = (warp >> 1) * 32, wn = (warp & 1) * 32;
    int r = t >> 2, c4 = (t & 3) * 4;
    int kr = t >> 4, vc4 = (t & 15) * 4;

    const float* A0 = P + (size_t)(m0 + r) * SEQ;
    const float* A1 = P + (size_t)(m0 + r + 64) * SEQ;

    float acc[2][4][4] = {};
    {
        float4 a0 = *(const float4*)(A0 + c4);
        float4 a1 = *(const float4*)(A1 + c4);
        float4 v  = *(const float4*)(V + (size_t)kr * QKVC + vc4);
        As[0][r][c4+0]=to_tf32(a0.x); As[0][r][c4+1]=to_tf32(a0.y);
        As[0][r][c4+2]=to_tf32(a0.z); As[0][r][c4+3]=to_tf32(a0.w);
        As[0][r+64][c4+0]=to_tf32(a1.x); As[0][r+64][c4+1]=to_tf32(a1.y);
        As[0][r+64][c4+2]=to_tf32(a1.z); As[0][r+64][c4+3]=to_tf32(a1.w);
        Vs[0][kr][vc4+0]=to_tf32(v.x); Vs[0][kr][vc4+1]=to_tf32(v.y);
        Vs[0][kr][vc4+2]=to_tf32(v.z); Vs[0][kr][vc4+3]=to_tf32(v.w);
    }
    __syncthreads();

    const int NT = SEQ / 16;
    int buf = 0;
    for (int kt = 0; kt < NT; kt++) {
        float4 na0, na1, nv;
        bool nxt = (kt + 1) < NT;
        if (nxt) {
            int k0 = (kt + 1) * 16;
            na0 = *(const float4*)(A0 + k0 + c4);
            na1 = *(const float4*)(A1 + k0 + c4);
            nv  = *(const float4*)(V + (size_t)(k0 + kr) * QKVC + vc4);
        }
        /* compute */
        #pragma unroll
        for (int kc = 0; kc < 2; kc++) {
            int kb = kc * 8;
            float a[2][4], bfr[4][2];
            #pragma unroll
            for (int mi = 0; mi < 2; mi++) {
                a[mi][0] = As[buf][wm + mi*16 + lr    ][kb + lc];
                a[mi][1] = As[buf][wm + mi*16 + lr + 8][kb + lc];
                a[mi][2] = As[buf][wm + mi*16 + lr    ][kb + lc + 4];
                a[mi][3] = As[buf][wm + mi*16 + lr + 8][kb + lc + 4];
            }
            #pragma unroll
            for (int ni = 0; ni < 4; ni++) {
                bfr[ni][0] = Vs[buf][kb + lc    ][wn + ni*8 + lr];
                bfr[ni][1] = Vs[buf][kb + lc + 4][wn + ni*8 + lr];
            }
            #pragma unroll
            for (int mi = 0; mi < 2; mi++)
                #pragma unroll
                for (int ni = 0; ni < 4; ni++)
                    mma8(acc[mi][ni], a[mi], bfr[ni]);
        }
        if (nxt) {
            int nb = buf ^ 1;
            As[nb][r][c4+0]=to_tf32(na0.x); As[nb][r][c4+1]=to_tf32(na0.y);
            As[nb][r][c4+2]=to_tf32(na0.z); As[nb][r][c4+3]=to_tf32(na0.w);
            As[nb][r+64][c4+0]=to_tf32(na1.x); As[nb][r+64][c4+1]=to_tf32(na1.y);
            As[nb][r+64][c4+2]=to_tf32(na1.z); As[nb][r+64][c4+3]=to_tf32(na1.w);
            Vs[nb][kr][vc4+0]=to_tf32(nv.x); Vs[nb][kr][vc4+1]=to_tf32(nv.y);
            Vs[nb][kr][vc4+2]=to_tf32(nv.z); Vs[nb][kr][vc4+3]=to_tf32(nv.w);
        }
        __syncthreads();
        buf ^= 1;
    }
    #pragma unroll
    for (int mi = 0; mi < 2; mi++)
        #pragma unroll
        for (int ni = 0; ni < 4; ni++) {
            int row = m0 + wm + mi*16 + lr;
            int col = wn + ni*8 + lc*2;
            out[((size_t)b * SEQ + row) * CH + h*HD + col    ] = acc[mi][ni][0];
            out[((size_t)b * SEQ + row) * CH + h*HD + col + 1] = acc[mi][ni][1];
            out[((size_t)b * SEQ + row + 8) * CH + h*HD + col    ] = acc[mi][ni][2];
            out[((size_t)b * SEQ + row + 8) * CH + h*HD + col + 1] = acc[mi][ni][3];
        }
}

extern "C" void kernel_launch(void* const* d_in, const int* in_sizes, int n_in,
                              void* d_out, int out_size) {
    const float* x     = (const float*)d_in[0];
    const float* qkv_w = (const float*)d_in[1];
    const float* qkv_b = (const float*)d_in[2];
    const float* ln_g  = (const float*)d_in[3];
    const float* ln_b  = (const float*)d_in[4];
    float* out = (float*)d_out;

    ln_kernel<<<ROWS, 256>>>(x, ln_g, ln_b);
    qkv_gemm<<<dim3(QKVC / 64, ROWS / 128), 256>>>(qkv_w, qkv_b);
    score_gemm<<<dim3(SEQ / 64, SEQ / 128, BH), 256>>>();
    conv_softmax_v2<<<dim3(SEQ / CR, BH), 256>>>();
    pv_gemm<<<dim3(SEQ / 128, BH), 256>>>(out);
}

// round 9
// speedup vs baseline: 1.1510x; 1.1470x over previous
#include <cuda_runtime.h>
#include <cuda_fp16.h>
#include <math.h>

#define BN   4
#define SEQ  1024
#define CH   768
#define NH   12
#define HD   64
#define ROWS (BN*SEQ)
#define QKVC (3*CH)
#define BH   (BN*NH)
#define BETA 0.2f
#define SCALE 0.125f
#define LN_EPS 1e-5f

__device__ float  g_xn[(size_t)ROWS * CH];
__device__ float  g_qkv[(size_t)ROWS * QKVC];
__device__ float  g_S[(size_t)BH * SEQ * SEQ];
__device__ __half g_Ph[(size_t)BH * SEQ * SEQ];

__device__ __forceinline__ float to_tf32(float x) {
    unsigned u;
    asm("cvt.rna.tf32.f32 %0, %1;" : "=r"(u) : "f"(x));
    return __uint_as_float(u);
}
__device__ __forceinline__ void mma8(float* c, const float* a, const float* b) {
    asm volatile(
        "mma.sync.aligned.m16n8k8.row.col.f32.tf32.tf32.f32 "
        "{%0,%1,%2,%3}, {%4,%5,%6,%7}, {%8,%9}, {%0,%1,%2,%3};"
        : "+f"(c[0]), "+f"(c[1]), "+f"(c[2]), "+f"(c[3])
        : "r"(__float_as_uint(a[0])), "r"(__float_as_uint(a[1])),
          "r"(__float_as_uint(a[2])), "r"(__float_as_uint(a[3])),
          "r"(__float_as_uint(b[0])), "r"(__float_as_uint(b[1])));
}
__device__ __forceinline__ void mma16(float* c, const unsigned* a,
                                      unsigned b0, unsigned b1) {
    asm volatile(
        "mma.sync.aligned.m16n8k16.row.col.f32.f16.f16.f32 "
        "{%0,%1,%2,%3}, {%4,%5,%6,%7}, {%8,%9}, {%0,%1,%2,%3};"
        : "+f"(c[0]), "+f"(c[1]), "+f"(c[2]), "+f"(c[3])
        : "r"(a[0]), "r"(a[1]), "r"(a[2]), "r"(a[3]), "r"(b0), "r"(b1));
}

/* ================= LayerNorm: one block per token ================= */
__global__ void ln_kernel(const float* __restrict__ x,
                          const float* __restrict__ gamma,
                          const float* __restrict__ beta) {
    int row = blockIdx.x;
    const float* xr = x + (size_t)row * CH;
    float*       orow = g_xn + (size_t)row * CH;
    int t = threadIdx.x;

    float v0 = xr[t], v1 = xr[t + 256], v2 = xr[t + 512];
    float s  = v0 + v1 + v2;
    float sq = v0 * v0 + v1 * v1 + v2 * v2;

    __shared__ float redS[8], redQ[8], stats[2];
    #pragma unroll
    for (int o = 16; o; o >>= 1) {
        s  += __shfl_down_sync(0xffffffffu, s,  o);
        sq += __shfl_down_sync(0xffffffffu, sq, o);
    }
    int w = t >> 5, l = t & 31;
    if (l == 0) { redS[w] = s; redQ[w] = sq; }
    __syncthreads();
    if (t == 0) {
        float S = 0.f, Q = 0.f;
        #pragma unroll
        for (int i = 0; i < 8; i++) { S += redS[i]; Q += redQ[i]; }
        float mu  = S * (1.0f / CH);
        float var = Q * (1.0f / CH) - mu * mu;
        stats[0] = mu;
        stats[1] = rsqrtf(var + LN_EPS);
    }
    __syncthreads();
    float mu = stats[0], rs = stats[1];
    orow[t]       = (v0 - mu) * rs * gamma[t]       + beta[t];
    orow[t + 256] = (v1 - mu) * rs * gamma[t + 256] + beta[t + 256];
    orow[t + 512] = (v2 - mu) * rs * gamma[t + 512] + beta[t + 512];
}

/* ===== shared helpers for 128x128 tf32 GEMM (8 warps, warp 32x64) ===== */
#define STORE4(ARR, ROWI, va)                                             \
    ARR[ROWI][c4+0]=to_tf32(va.x); ARR[ROWI][c4+1]=to_tf32(va.y);         \
    ARR[ROWI][c4+2]=to_tf32(va.z); ARR[ROWI][c4+3]=to_tf32(va.w);

#define COMPUTE128(AS, BS)                                                \
    _Pragma("unroll")                                                     \
    for (int kc = 0; kc < 2; kc++) {                                      \
        int kb = kc * 8;                                                  \
        float a[2][4];                                                    \
        _Pragma("unroll")                                                 \
        for (int mi = 0; mi < 2; mi++) {                                  \
            a[mi][0] = AS[wm + mi*16 + lr    ][kb + lc];                  \
            a[mi][1] = AS[wm + mi*16 + lr + 8][kb + lc];                  \
            a[mi][2] = AS[wm + mi*16 + lr    ][kb + lc + 4];              \
            a[mi][3] = AS[wm + mi*16 + lr + 8][kb + lc + 4];              \
        }                                                                 \
        _Pragma("unroll")                                                 \
        for (int ni = 0; ni < 8; ni++) {                                  \
            float bfr[2];                                                 \
            bfr[0] = BS[wn + ni*8 + lr][kb + lc];                         \
            bfr[1] = BS[wn + ni*8 + lr][kb + lc + 4];                     \
            _Pragma("unroll")                                             \
            for (int mi = 0; mi < 2; mi++)                                \
                mma8(acc[mi][ni], a[mi], bfr);                            \
        }                                                                 \
    }

/* ========== QKV GEMM (tf32 MMA, 128x128, double-buffered) ========== */
__global__ __launch_bounds__(256) void qkv_gemm(const float* __restrict__ W,
                                                const float* __restrict__ bias) {
    __shared__ float As[2][128][20];
    __shared__ float Bs[2][128][20];
    int m0 = blockIdx.y * 128, n0 = blockIdx.x * 128;
    int t = threadIdx.x;
    int warp = t >> 5, lane = t & 31, lr = lane >> 2, lc = lane & 3;
    int wm = (warp >> 1) * 32, wn = (warp & 1) * 64;
    int r = t >> 2, c4 = (t & 3) * 4;

    const float* A0 = g_xn + (size_t)(m0 + r) * CH;
    const float* A1 = A0 + (size_t)64 * CH;
    const float* B0 = W + (size_t)(n0 + r) * CH;
    const float* B1 = B0 + (size_t)64 * CH;

    float acc[2][8][4] = {};
    {
        float4 a0 = *(const float4*)(A0 + c4);
        float4 a1 = *(const float4*)(A1 + c4);
        float4 b0 = *(const float4*)(B0 + c4);
        float4 b1 = *(const float4*)(B1 + c4);
        STORE4(As[0], r, a0) STORE4(As[0], r + 64, a1)
        STORE4(Bs[0], r, b0) STORE4(Bs[0], r + 64, b1)
    }
    __syncthreads();

    const int NT = CH / 16;
    int buf = 0;
    for (int kt = 0; kt < NT; kt++) {
        float4 na0, na1, nb0, nb1;
        bool nxt = (kt + 1) < NT;
        if (nxt) {
            int k0 = (kt + 1) * 16;
            na0 = *(const float4*)(A0 + k0 + c4);
            na1 = *(const float4*)(A1 + k0 + c4);
            nb0 = *(const float4*)(B0 + k0 + c4);
            nb1 = *(const float4*)(B1 + k0 + c4);
        }
        COMPUTE128(As[buf], Bs[buf])
        if (nxt) {
            int nb = buf ^ 1;
            STORE4(As[nb], r, na0) STORE4(As[nb], r + 64, na1)
            STORE4(Bs[nb], r, nb0) STORE4(Bs[nb], r + 64, nb1)
        }
        __syncthreads();
        buf ^= 1;
    }
    #pragma unroll
    for (int mi = 0; mi < 2; mi++)
        #pragma unroll
        for (int ni = 0; ni < 8; ni++) {
            int row = m0 + wm + mi*16 + lr;
            int col = n0 + wn + ni*8 + lc*2;
            g_qkv[(size_t)row * QKVC + col    ] = acc[mi][ni][0] + bias[col];
            g_qkv[(size_t)row * QKVC + col + 1] = acc[mi][ni][1] + bias[col+1];
            g_qkv[(size_t)(row+8) * QKVC + col    ] = acc[mi][ni][2] + bias[col];
            g_qkv[(size_t)(row+8) * QKVC + col + 1] = acc[mi][ni][3] + bias[col+1];
        }
}

/* ========== Scores (tf32 MMA, 128x128, double-buffered) ========== */
__global__ __launch_bounds__(256) void score_gemm() {
    int bh = blockIdx.z, b = bh / NH, h = bh % NH;
    const float* Q = g_qkv + (size_t)b * SEQ * QKVC + h * HD;
    const float* K = g_qkv + (size_t)b * SEQ * QKVC + CH + h * HD;
    float* S = g_S + (size_t)bh * SEQ * SEQ;

    __shared__ float As[2][128][20];
    __shared__ float Bs[2][128][20];
    int m0 = blockIdx.y * 128, n0 = blockIdx.x * 128;
    int t = threadIdx.x;
    int warp = t >> 5, lane = t & 31, lr = lane >> 2, lc = lane & 3;
    int wm = (warp >> 1) * 32, wn = (warp & 1) * 64;
    int r = t >> 2, c4 = (t & 3) * 4;

    const float* A0 = Q + (size_t)(m0 + r) * QKVC;
    const float* A1 = A0 + (size_t)64 * QKVC;
    const float* B0 = K + (size_t)(n0 + r) * QKVC;
    const float* B1 = B0 + (size_t)64 * QKVC;

    float acc[2][8][4] = {};
    {
        float4 a0 = *(const float4*)(A0 + c4);
        float4 a1 = *(const float4*)(A1 + c4);
        float4 b0 = *(const float4*)(B0 + c4);
        float4 b1 = *(const float4*)(B1 + c4);
        STORE4(As[0], r, a0) STORE4(As[0], r + 64, a1)
        STORE4(Bs[0], r, b0) STORE4(Bs[0], r + 64, b1)
    }
    __syncthreads();

    const int NT = HD / 16;
    int buf = 0;
    for (int kt = 0; kt < NT; kt++) {
        float4 na0, na1, nb0, nb1;
        bool nxt = (kt + 1) < NT;
        if (nxt) {
            int k0 = (kt + 1) * 16;
            na0 = *(const float4*)(A0 + k0 + c4);
            na1 = *(const float4*)(A1 + k0 + c4);
            nb0 = *(const float4*)(B0 + k0 + c4);
            nb1 = *(const float4*)(B1 + k0 + c4);
        }
        COMPUTE128(As[buf], Bs[buf])
        if (nxt) {
            int nb = buf ^ 1;
            STORE4(As[nb], r, na0) STORE4(As[nb], r + 64, na1)
            STORE4(Bs[nb], r, nb0) STORE4(Bs[nb], r + 64, nb1)
        }
        __syncthreads();
        buf ^= 1;
    }
    #pragma unroll
    for (int mi = 0; mi < 2; mi++)
        #pragma unroll
        for (int ni = 0; ni < 8; ni++) {
            int row = m0 + wm + mi*16 + lr;
            int col = n0 + wn + ni*8 + lc*2;
            S[(size_t)row * SEQ + col    ] = acc[mi][ni][0] * SCALE;
            S[(size_t)row * SEQ + col + 1] = acc[mi][ni][1] * SCALE;
            S[(size_t)(row+8) * SEQ + col    ] = acc[mi][ni][2] * SCALE;
            S[(size_t)(row+8) * SEQ + col + 1] = acc[mi][ni][3] * SCALE;
        }
}

/* ============ Lateral inhibition conv + row softmax (fp16 out) ============ */
#define CR 4
__global__ __launch_bounds__(256) void conv_softmax_v2() {
    int bh = blockIdx.y;
    int i0 = blockIdx.x * CR;
    const float* S = g_S + (size_t)bh * SEQ * SEQ;
    __half*      P = g_Ph + (size_t)bh * SEQ * SEQ;

    __shared__ float rows[6][SEQ];
    __shared__ float red[CR][8];
    __shared__ float bc[CR];

    int t = threadIdx.x, lane = t & 31, w = t >> 5;
    int j0 = t * 4;

    #pragma unroll
    for (int r = 0; r < 6; r++) {
        int gi = i0 - 1 + r;
        float4 v = make_float4(0.f, 0.f, 0.f, 0.f);
        if (gi >= 0 && gi < SEQ) v = *(const float4*)(S + (size_t)gi * SEQ + j0);
        *(float4*)&rows[r][j0] = v;
    }
    __syncthreads();

    float a[CR][4], mx[CR];
    #pragma unroll
    for (int r = 0; r < CR; r++) {
        float4 x = *(const float4*)&rows[r    ][j0];
        float4 y = *(const float4*)&rows[r + 1][j0];
        float4 z = *(const float4*)&rows[r + 2][j0];
        float4 vs;
        vs.x = x.x + y.x + z.x;  vs.y = x.y + y.y + z.y;
        vs.z = x.z + y.z + z.z;  vs.w = x.w + y.w + z.w;

        float left  = __shfl_up_sync(0xffffffffu, vs.w, 1);
        float right = __shfl_down_sync(0xffffffffu, vs.x, 1);
        if (lane == 0) {
            int j = j0 - 1;
            left = (j >= 0) ? rows[r][j] + rows[r + 1][j] + rows[r + 2][j] : 0.f;
        }
        if (lane == 31) {
            int j = j0 + 4;
            right = (j < SEQ) ? rows[r][j] + rows[r + 1][j] + rows[r + 2][j] : 0.f;
        }

        a[r][0] = (1.0f + BETA) * y.x - BETA * (left + vs.x + vs.y);
        a[r][1] = (1.0f + BETA) * y.y - BETA * (vs.x + vs.y + vs.z);
        a[r][2] = (1.0f + BETA) * y.z - BETA * (vs.y + vs.z + vs.w);
        a[r][3] = (1.0f + BETA) * y.w - BETA * (vs.z + vs.w + right);
        mx[r] = fmaxf(fmaxf(a[r][0], a[r][1]), fmaxf(a[r][2], a[r][3]));
    }

    #pragma unroll
    for (int r = 0; r < CR; r++) {
        float m = mx[r];
        #pragma unroll
        for (int o = 16; o; o >>= 1) m = fmaxf(m, __shfl_xor_sync(0xffffffffu, m, o));
        if (lane == 0) red[r][w] = m;
    }
    __syncthreads();
    if (t < CR) {
        float m = red[t][0];
        #pragma unroll
        for (int k = 1; k < 8; k++) m = fmaxf(m, red[t][k]);
        bc[t] = m;
    }
    __syncthreads();

    float sm[CR];
    #pragma unroll
    for (int r = 0; r < CR; r++) {
        float M = bc[r];
        float s = 0.f;
        #pragma unroll
        for (int q = 0; q < 4; q++) { a[r][q] = __expf(a[r][q] - M); s += a[r][q]; }
        sm[r] = s;
    }
    __syncthreads();
    #pragma unroll
    for (int r = 0; r < CR; r++) {
        float s = sm[r];
        #pragma unroll
        for (int o = 16; o; o >>= 1) s += __shfl_xor_sync(0xffffffffu, s, o);
        if (lane == 0) red[r][w] = s;
    }
    __syncthreads();
    if (t < CR) {
        float s = 0.f;
        #pragma unroll
        for (int k = 0; k < 8; k++) s += red[t][k];
        bc[t] = 1.0f / s;
    }
    __syncthreads();

    #pragma unroll
    for (int r = 0; r < CR; r++) {
        float inv = bc[r];
        __half2 h01 = __floats2half2_rn(a[r][0] * inv, a[r][1] * inv);
        __half2 h23 = __floats2half2_rn(a[r][2] * inv, a[r][3] * inv);
        uint2 u;
        u.x = *(unsigned*)&h01;
        u.y = *(unsigned*)&h23;
        *(uint2*)(P + (size_t)(i0 + r) * SEQ + j0) = u;
    }
}

/* ========== PV GEMM (fp16 MMA m16n8k16): out = P @ V ========== */
__global__ __launch_bounds__(256) void pv_gemm(float* __restrict__ out) {
    int bh = blockIdx.y, b = bh / NH, h = bh % NH;
    const __half* Pg = g_Ph + (size_t)bh * SEQ * SEQ;
    const float*  V  = g_qkv + (size_t)b * SEQ * QKVC + 2 * CH + h * HD;
    int m0 = blockIdx.x * 128;

    __shared__ unsigned Ps[128][10];   /* 8 half2-pairs per 16-k tile + pad */
    __shared__ unsigned Vsu[64][10];

    int t = threadIdx.x;
    int warp = t >> 5, lane = t & 31, lr = lane >> 2, lc = lane & 3;
    int wm = (warp >> 1) * 32, wn = (warp & 1) * 32;
    int pr = t >> 1, ph = (t & 1) * 4;          /* P staging: row, uint offset */
    int kp = (t & 127) >> 4, n4 = t & 15;       /* V staging (t<128) */

    float acc[2][4][4] = {};

    for (int kt = 0; kt < SEQ / 16; kt++) {
        int k0 = kt * 16;
        uint4 pv4 = *(const uint4*)(Pg + (size_t)(m0 + pr) * SEQ + k0 + (t & 1) * 8);
        if (t < 128) {
            float4 lo = *(const float4*)(V + (size_t)(k0 + 2*kp    ) * QKVC + n4 * 4);
            float4 hi = *(const float4*)(V + (size_t)(k0 + 2*kp + 1) * QKVC + n4 * 4);
            __half2 p0 = __floats2half2_rn(lo.x, hi.x);
            __half2 p1 = __floats2half2_rn(lo.y, hi.y);
            __half2 p2 = __floats2half2_rn(lo.z, hi.z);
            __half2 p3 = __floats2half2_rn(lo.w, hi.w);
            Vsu[n4*4 + 0][kp] = *(unsigned*)&p0;
            Vsu[n4*4 + 1][kp] = *(unsigned*)&p1;
            Vsu[n4*4 + 2][kp] = *(unsigned*)&p2;
            Vsu[n4*4 + 3][kp] = *(unsigned*)&p3;
        }
        Ps[pr][ph + 0] = pv4.x; Ps[pr][ph + 1] = pv4.y;
        Ps[pr][ph + 2] = pv4.z; Ps[pr][ph + 3] = pv4.w;
        __syncthreads();

        unsigned a[2][4];
        #pragma unroll
        for (int mi = 0; mi < 2; mi++) {
            a[mi][0] = Ps[wm + mi*16 + lr    ][lc];
            a[mi][1] = Ps[wm + mi*16 + lr + 8][lc];
            a[mi][2] = Ps[wm + mi*16 + lr    ][lc + 4];
            a[mi][3] = Ps[wm + mi*16 + lr + 8][lc + 4];
        }
        #pragma unroll
        for (int ni = 0; ni < 4; ni++) {
            unsigned b0 = Vsu[wn + ni*8 + lr][lc];
            unsigned b1 = Vsu[wn + ni*8 + lr][lc + 4];
            #pragma unroll
            for (int mi = 0; mi < 2; mi++)
                mma16(acc[mi][ni], a[mi], b0, b1);
        }
        __syncthreads();
    }

    #pragma unroll
    for (int mi = 0; mi < 2; mi++)
        #pragma unroll
        for (int ni = 0; ni < 4; ni++) {
            int row = m0 + wm + mi*16 + lr;
            int col = wn + ni*8 + lc*2;
            out[((size_t)b * SEQ + row) * CH + h*HD + col    ] = acc[mi][ni][0];
            out[((size_t)b * SEQ + row) * CH + h*HD + col + 1] = acc[mi][ni][1];
            out[((size_t)b * SEQ + row + 8) * CH + h*HD + col    ] = acc[mi][ni][2];
            out[((size_t)b * SEQ + row + 8) * CH + h*HD + col + 1] = acc[mi][ni][3];
        }
}

extern "C" void kernel_launch(void* const* d_in, const int* in_sizes, int n_in,
                              void* d_out, int out_size) {
    const float* x     = (const float*)d_in[0];
    const float* qkv_w = (const float*)d_in[1];
    const float* qkv_b = (const float*)d_in[2];
    const float* ln_g  = (const float*)d_in[3];
    const float* ln_b  = (const float*)d_in[4];
    float* out = (float*)d_out;

    ln_kernel<<<ROWS, 256>>>(x, ln_g, ln_b);
    qkv_gemm<<<dim3(QKVC / 128, ROWS / 128), 256>>>(qkv_w, qkv_b);
    score_gemm<<<dim3(SEQ / 128, SEQ / 128, BH), 256>>>();
    conv_softmax_v2<<<dim3(SEQ / CR, BH), 256>>>();
    pv_gemm<<<dim3(SEQ / 128, BH), 256>>>(out);
}

// round 10
// speedup vs baseline: 1.3961x; 1.2130x over previous
#include <cuda_runtime.h>
#include <cuda_fp16.h>
#include <math.h>

#define BN   4
#define SEQ  1024
#define CH   768
#define NH   12
#define HD   64
#define ROWS (BN*SEQ)
#define QKVC (3*CH)
#define BH   (BN*NH)
#define BETA 0.2f
#define SCALE 0.125f
#define LN_EPS 1e-5f

__device__ __half g_xnh[(size_t)ROWS * CH];
__device__ __half g_Wh[(size_t)QKVC * CH];
__device__ __half g_qkvh[(size_t)ROWS * QKVC];
__device__ float  g_S[(size_t)BH * SEQ * SEQ];
__device__ __half g_Ph[(size_t)BH * SEQ * SEQ];

__device__ __forceinline__ void mma16(float* c, const unsigned* a,
                                      unsigned b0, unsigned b1) {
    asm volatile(
        "mma.sync.aligned.m16n8k16.row.col.f32.f16.f16.f32 "
        "{%0,%1,%2,%3}, {%4,%5,%6,%7}, {%8,%9}, {%0,%1,%2,%3};"
        : "+f"(c[0]), "+f"(c[1]), "+f"(c[2]), "+f"(c[3])
        : "r"(a[0]), "r"(a[1]), "r"(a[2]), "r"(a[3]), "r"(b0), "r"(b1));
}

/* ================= W -> half ================= */
__global__ void wcvt_kernel(const float* __restrict__ W) {
    int i = (blockIdx.x * 256 + threadIdx.x) * 4;
    float4 v = *(const float4*)(W + i);
    __half2 h0 = __floats2half2_rn(v.x, v.y);
    __half2 h1 = __floats2half2_rn(v.z, v.w);
    uint2 u; u.x = *(unsigned*)&h0; u.y = *(unsigned*)&h1;
    *(uint2*)(g_Wh + i) = u;
}

/* ================= LayerNorm: one block per token, half out ================= */
__global__ void ln_kernel(const float* __restrict__ x,
                          const float* __restrict__ gamma,
                          const float* __restrict__ beta) {
    int row = blockIdx.x;
    const float* xr = x + (size_t)row * CH;
    __half*      orow = g_xnh + (size_t)row * CH;
    int t = threadIdx.x;

    float v0 = xr[t], v1 = xr[t + 256], v2 = xr[t + 512];
    float s  = v0 + v1 + v2;
    float sq = v0 * v0 + v1 * v1 + v2 * v2;

    __shared__ float redS[8], redQ[8], stats[2];
    #pragma unroll
    for (int o = 16; o; o >>= 1) {
        s  += __shfl_down_sync(0xffffffffu, s,  o);
        sq += __shfl_down_sync(0xffffffffu, sq, o);
    }
    int w = t >> 5, l = t & 31;
    if (l == 0) { redS[w] = s; redQ[w] = sq; }
    __syncthreads();
    if (t == 0) {
        float S = 0.f, Q = 0.f;
        #pragma unroll
        for (int i = 0; i < 8; i++) { S += redS[i]; Q += redQ[i]; }
        float mu  = S * (1.0f / CH);
        float var = Q * (1.0f / CH) - mu * mu;
        stats[0] = mu;
        stats[1] = rsqrtf(var + LN_EPS);
    }
    __syncthreads();
    float mu = stats[0], rs = stats[1];
    orow[t]       = __float2half_rn((v0 - mu) * rs * gamma[t]       + beta[t]);
    orow[t + 256] = __float2half_rn((v1 - mu) * rs * gamma[t + 256] + beta[t + 256]);
    orow[t + 512] = __float2half_rn((v2 - mu) * rs * gamma[t + 512] + beta[t + 512]);
}

/* ===== fp16 128x128 GEMM compute step (8 warps, warp 32x64) =====
   smem layout: [row][uint(=half2) k-index], 8 uints per k16 tile + 2 pad */
#define COMPUTE128H(AS, BS)                                               \
    {                                                                     \
        unsigned a[2][4];                                                 \
        _Pragma("unroll")                                                 \
        for (int mi = 0; mi < 2; mi++) {                                  \
            a[mi][0] = AS[wm + mi*16 + lr    ][lc];                       \
            a[mi][1] = AS[wm + mi*16 + lr + 8][lc];                       \
            a[mi][2] = AS[wm + mi*16 + lr    ][lc + 4];                   \
            a[mi][3] = AS[wm + mi*16 + lr + 8][lc + 4];                   \
        }                                                                 \
        _Pragma("unroll")                                                 \
        for (int ni = 0; ni < 8; ni++) {                                  \
            unsigned b0 = BS[wn + ni*8 + lr][lc];                         \
            unsigned b1 = BS[wn + ni*8 + lr][lc + 4];                     \
            _Pragma("unroll")                                             \
            for (int mi = 0; mi < 2; mi++)                                \
                mma16(acc[mi][ni], a[mi], b0, b1);                        \
        }                                                                 \
    }

#define STAGE_U4(ARR, ROWI, U4OFF, v4)                                    \
    ARR[ROWI][U4OFF + 0] = v4.x; ARR[ROWI][U4OFF + 1] = v4.y;             \
    ARR[ROWI][U4OFF + 2] = v4.z; ARR[ROWI][U4OFF + 3] = v4.w;

/* ========== QKV GEMM (fp16 MMA, 128x128, double-buffered) ========== */
__global__ __launch_bounds__(256) void qkv_gemm(const float* __restrict__ bias) {
    __shared__ unsigned As[2][128][10];
    __shared__ unsigned Bs[2][128][10];
    int m0 = blockIdx.y * 128, n0 = blockIdx.x * 128;
    int t = threadIdx.x;
    int warp = t >> 5, lane = t & 31, lr = lane >> 2, lc = lane & 3;
    int wm = (warp >> 1) * 32, wn = (warp & 1) * 64;
    int sr = t >> 1, so = (t & 1) * 4;          /* staging row, uint offset */
    int sh = (t & 1) * 8;                       /* half offset in source   */

    const __half* A0 = g_xnh + (size_t)(m0 + sr) * CH + sh;
    const __half* B0 = g_Wh  + (size_t)(n0 + sr) * CH + sh;

    float acc[2][8][4] = {};
    {
        uint4 av = *(const uint4*)A0;
        uint4 bv = *(const uint4*)B0;
        STAGE_U4(As[0], sr, so, av)
        STAGE_U4(Bs[0], sr, so, bv)
    }
    __syncthreads();

    const int NT = CH / 16;
    int buf = 0;
    for (int kt = 0; kt < NT; kt++) {
        uint4 nav, nbv;
        bool nxt = (kt + 1) < NT;
        if (nxt) {
            int k0 = (kt + 1) * 16;
            nav = *(const uint4*)(A0 + k0);
            nbv = *(const uint4*)(B0 + k0);
        }
        COMPUTE128H(As[buf], Bs[buf])
        if (nxt) {
            int nb = buf ^ 1;
            STAGE_U4(As[nb], sr, so, nav)
            STAGE_U4(Bs[nb], sr, so, nbv)
        }
        __syncthreads();
        buf ^= 1;
    }
    #pragma unroll
    for (int mi = 0; mi < 2; mi++)
        #pragma unroll
        for (int ni = 0; ni < 8; ni++) {
            int row = m0 + wm + mi*16 + lr;
            int col = n0 + wn + ni*8 + lc*2;
            float b0 = bias[col], b1 = bias[col + 1];
            __half2 h0 = __floats2half2_rn(acc[mi][ni][0] + b0, acc[mi][ni][1] + b1);
            __half2 h1 = __floats2half2_rn(acc[mi][ni][2] + b0, acc[mi][ni][3] + b1);
            *(unsigned*)(g_qkvh + (size_t)row * QKVC + col)     = *(unsigned*)&h0;
            *(unsigned*)(g_qkvh + (size_t)(row+8) * QKVC + col) = *(unsigned*)&h1;
        }
}

/* ========== Scores (fp16 MMA, 128x128) ========== */
__global__ __launch_bounds__(256) void score_gemm() {
    int bh = blockIdx.z, b = bh / NH, h = bh % NH;
    const __half* Q = g_qkvh + (size_t)b * SEQ * QKVC + h * HD;
    const __half* K = g_qkvh + (size_t)b * SEQ * QKVC + CH + h * HD;
    float* S = g_S + (size_t)bh * SEQ * SEQ;

    __shared__ unsigned As[128][10];
    __shared__ unsigned Bs[128][10];
    int m0 = blockIdx.y * 128, n0 = blockIdx.x * 128;
    int t = threadIdx.x;
    int warp = t >> 5, lane = t & 31, lr = lane >> 2, lc = lane & 3;
    int wm = (warp >> 1) * 32, wn = (warp & 1) * 64;
    int sr = t >> 1, so = (t & 1) * 4, sh = (t & 1) * 8;

    const __half* A0 = Q + (size_t)(m0 + sr) * QKVC + sh;
    const __half* B0 = K + (size_t)(n0 + sr) * QKVC + sh;

    float acc[2][8][4] = {};
    #pragma unroll
    for (int kt = 0; kt < HD / 16; kt++) {
        int k0 = kt * 16;
        uint4 av = *(const uint4*)(A0 + k0);
        uint4 bv = *(const uint4*)(B0 + k0);
        STAGE_U4(As, sr, so, av)
        STAGE_U4(Bs, sr, so, bv)
        __syncthreads();
        COMPUTE128H(As, Bs)
        __syncthreads();
    }
    #pragma unroll
    for (int mi = 0; mi < 2; mi++)
        #pragma unroll
        for (int ni = 0; ni < 8; ni++) {
            int row = m0 + wm + mi*16 + lr;
            int col = n0 + wn + ni*8 + lc*2;
            float2 v0 = make_float2(acc[mi][ni][0] * SCALE, acc[mi][ni][1] * SCALE);
            float2 v1 = make_float2(acc[mi][ni][2] * SCALE, acc[mi][ni][3] * SCALE);
            *(float2*)(S + (size_t)row * SEQ + col)     = v0;
            *(float2*)(S + (size_t)(row+8) * SEQ + col) = v1;
        }
}

/* ============ Lateral inhibition conv + row softmax (fp16 out) ============ */
#define CR 4
__global__ __launch_bounds__(256) void conv_softmax_v2() {
    int bh = blockIdx.y;
    int i0 = blockIdx.x * CR;
    const float* S = g_S + (size_t)bh * SEQ * SEQ;
    __half*      P = g_Ph + (size_t)bh * SEQ * SEQ;

    __shared__ float rows[6][SEQ];
    __shared__ float red[CR][8];
    __shared__ float bc[CR];

    int t = threadIdx.x, lane = t & 31, w = t >> 5;
    int j0 = t * 4;

    #pragma unroll
    for (int r = 0; r < 6; r++) {
        int gi = i0 - 1 + r;
        float4 v = make_float4(0.f, 0.f, 0.f, 0.f);
        if (gi >= 0 && gi < SEQ) v = *(const float4*)(S + (size_t)gi * SEQ + j0);
        *(float4*)&rows[r][j0] = v;
    }
    __syncthreads();

    float a[CR][4], mx[CR];
    #pragma unroll
    for (int r = 0; r < CR; r++) {
        float4 x = *(const float4*)&rows[r    ][j0];
        float4 y = *(const float4*)&rows[r + 1][j0];
        float4 z = *(const float4*)&rows[r + 2][j0];
        float4 vs;
        vs.x = x.x + y.x + z.x;  vs.y = x.y + y.y + z.y;
        vs.z = x.z + y.z + z.z;  vs.w = x.w + y.w + z.w;

        float left  = __shfl_up_sync(0xffffffffu, vs.w, 1);
        float right = __shfl_down_sync(0xffffffffu, vs.x, 1);
        if (lane == 0) {
            int j = j0 - 1;
            left = (j >= 0) ? rows[r][j] + rows[r + 1][j] + rows[r + 2][j] : 0.f;
        }
        if (lane == 31) {
            int j = j0 + 4;
            right = (j < SEQ) ? rows[r][j] + rows[r + 1][j] + rows[r + 2][j] : 0.f;
        }

        a[r][0] = (1.0f + BETA) * y.x - BETA * (left + vs.x + vs.y);
        a[r][1] = (1.0f + BETA) * y.y - BETA * (vs.x + vs.y + vs.z);
        a[r][2] = (1.0f + BETA) * y.z - BETA * (vs.y + vs.z + vs.w);
        a[r][3] = (1.0f + BETA) * y.w - BETA * (vs.z + vs.w + right);
        mx[r] = fmaxf(fmaxf(a[r][0], a[r][1]), fmaxf(a[r][2], a[r][3]));
    }

    #pragma unroll
    for (int r = 0; r < CR; r++) {
        float m = mx[r];
        #pragma unroll
        for (int o = 16; o; o >>= 1) m = fmaxf(m, __shfl_xor_sync(0xffffffffu, m, o));
        if (lane == 0) red[r][w] = m;
    }
    __syncthreads();
    if (t < CR) {
        float m = red[t][0];
        #pragma unroll
        for (int k = 1; k < 8; k++) m = fmaxf(m, red[t][k]);
        bc[t] = m;
    }
    __syncthreads();

    float sm[CR];
    #pragma unroll
    for (int r = 0; r < CR; r++) {
        float M = bc[r];
        float s = 0.f;
        #pragma unroll
        for (int q = 0; q < 4; q++) { a[r][q] = __expf(a[r][q] - M); s += a[r][q]; }
        sm[r] = s;
    }
    __syncthreads();
    #pragma unroll
    for (int r = 0; r < CR; r++) {
        float s = sm[r];
        #pragma unroll
        for (int o = 16; o; o >>= 1) s += __shfl_xor_sync(0xffffffffu, s, o);
        if (lane == 0) red[r][w] = s;
    }
    __syncthreads();
    if (t < CR) {
        float s = 0.f;
        #pragma unroll
        for (int k = 0; k < 8; k++) s += red[t][k];
        bc[t] = 1.0f / s;
    }
    __syncthreads();

    #pragma unroll
    for (int r = 0; r < CR; r++) {
        float inv = bc[r];
        __half2 h01 = __floats2half2_rn(a[r][0] * inv, a[r][1] * inv);
        __half2 h23 = __floats2half2_rn(a[r][2] * inv, a[r][3] * inv);
        uint2 u;
        u.x = *(unsigned*)&h01;
        u.y = *(unsigned*)&h23;
        *(uint2*)(P + (size_t)(i0 + r) * SEQ + j0) = u;
    }
}

/* ========== PV GEMM (fp16 MMA m16n8k16): out = P @ V ========== */
__global__ __launch_bounds__(256) void pv_gemm(float* __restrict__ out) {
    int bh = blockIdx.y, b = bh / NH, h = bh % NH;
    const __half* Pg = g_Ph + (size_t)bh * SEQ * SEQ;
    const __half* Vh = g_qkvh + (size_t)b * SEQ * QKVC + 2 * CH + h * HD;
    int m0 = blockIdx.x * 128;

    __shared__ unsigned Ps[128][10];
    __shared__ unsigned Vsu[64][10];

    int t = threadIdx.x;
    int warp = t >> 5, lane = t & 31, lr = lane >> 2, lc = lane & 3;
    int wm = (warp >> 1) * 32, wn = (warp & 1) * 32;
    int pr = t >> 1, ph = (t & 1) * 4;
    int kp = (t & 127) >> 4, n4 = t & 15;

    float acc[2][4][4] = {};

    for (int kt = 0; kt < SEQ / 16; kt++) {
        int k0 = kt * 16;
        uint4 pv4 = *(const uint4*)(Pg + (size_t)(m0 + pr) * SEQ + k0 + (t & 1) * 8);
        if (t < 128) {
            uint2 lo = *(const uint2*)(Vh + (size_t)(k0 + 2*kp    ) * QKVC + n4 * 4);
            uint2 hi = *(const uint2*)(Vh + (size_t)(k0 + 2*kp + 1) * QKVC + n4 * 4);
            const __half* lp = (const __half*)&lo;
            const __half* hp = (const __half*)&hi;
            #pragma unroll
            for (int i = 0; i < 4; i++) {
                __half2 pk = __halves2half2(lp[i], hp[i]);
                Vsu[n4*4 + i][kp] = *(unsigned*)&pk;
            }
        }
        Ps[pr][ph + 0] = pv4.x; Ps[pr][ph + 1] = pv4.y;
        Ps[pr][ph + 2] = pv4.z; Ps[pr][ph + 3] = pv4.w;
        __syncthreads();

        unsigned a[2][4];
        #pragma unroll
        for (int mi = 0; mi < 2; mi++) {
            a[mi][0] = Ps[wm + mi*16 + lr    ][lc];
            a[mi][1] = Ps[wm + mi*16 + lr + 8][lc];
            a[mi][2] = Ps[wm + mi*16 + lr    ][lc + 4];
            a[mi][3] = Ps[wm + mi*16 + lr + 8][lc + 4];
        }
        #pragma unroll
        for (int ni = 0; ni < 4; ni++) {
            unsigned b0 = Vsu[wn + ni*8 + lr][lc];
            unsigned b1 = Vsu[wn + ni*8 + lr][lc + 4];
            #pragma unroll
            for (int mi = 0; mi < 2; mi++)
                mma16(acc[mi][ni], a[mi], b0, b1);
        }
        __syncthreads();
    }

    #pragma unroll
    for (int mi = 0; mi < 2; mi++)
        #pragma unroll
        for (int ni = 0; ni < 4; ni++) {
            int row = m0 + wm + mi*16 + lr;
            int col = wn + ni*8 + lc*2;
            out[((size_t)b * SEQ + row) * CH + h*HD + col    ] = acc[mi][ni][0];
            out[((size_t)b * SEQ + row) * CH + h*HD + col + 1] = acc[mi][ni][1];
            out[((size_t)b * SEQ + row + 8) * CH + h*HD + col    ] = acc[mi][ni][2];
            out[((size_t)b * SEQ + row + 8) * CH + h*HD + col + 1] = acc[mi][ni][3];
        }
}

extern "C" void kernel_launch(void* const* d_in, const int* in_sizes, int n_in,
                              void* d_out, int out_size) {
    const float* x     = (const float*)d_in[0];
    const float* qkv_w = (const float*)d_in[1];
    const float* qkv_b = (const float*)d_in[2];
    const float* ln_g  = (const float*)d_in[3];
    const float* ln_b  = (const float*)d_in[4];
    float* out = (float*)d_out;

    wcvt_kernel<<<(QKVC * CH) / (256 * 4), 256>>>(qkv_w);
    ln_kernel<<<ROWS, 256>>>(x, ln_g, ln_b);
    qkv_gemm<<<dim3(QKVC / 128, ROWS / 128), 256>>>(qkv_b);
    score_gemm<<<dim3(SEQ / 128, SEQ / 128, BH), 256>>>();
    conv_softmax_v2<<<dim3(SEQ / CR, BH), 256>>>();
    pv_gemm<<<dim3(SEQ / 128, BH), 256>>>(out);
}

// round 11
// speedup vs baseline: 1.4471x; 1.0365x over previous
#include <cuda_runtime.h>
#include <cuda_fp16.h>
#include <math.h>

#define BN   4
#define SEQ  1024
#define CH   768
#define NH   12
#define HD   64
#define ROWS (BN*SEQ)
#define QKVC (3*CH)
#define BH   (BN*NH)
#define BETA 0.2f
#define SCALE 0.125f
#define LN_EPS 1e-5f

__device__ __half g_xnh[(size_t)ROWS * CH];
__device__ __half g_Wh[(size_t)QKVC * CH];
__device__ __half g_qkvh[(size_t)ROWS * QKVC];
__device__ float  g_S[(size_t)BH * SEQ * SEQ];
__device__ __half g_Ph[(size_t)BH * SEQ * SEQ];

__device__ __forceinline__ void mma16(float* c, const unsigned* a,
                                      unsigned b0, unsigned b1) {
    asm volatile(
        "mma.sync.aligned.m16n8k16.row.col.f32.f16.f16.f32 "
        "{%0,%1,%2,%3}, {%4,%5,%6,%7}, {%8,%9}, {%0,%1,%2,%3};"
        : "+f"(c[0]), "+f"(c[1]), "+f"(c[2]), "+f"(c[3])
        : "r"(a[0]), "r"(a[1]), "r"(a[2]), "r"(a[3]), "r"(b0), "r"(b1));
}

/* ================= W -> half ================= */
__global__ void wcvt_kernel(const float* __restrict__ W) {
    int i = (blockIdx.x * 256 + threadIdx.x) * 4;
    float4 v = *(const float4*)(W + i);
    __half2 h0 = __floats2half2_rn(v.x, v.y);
    __half2 h1 = __floats2half2_rn(v.z, v.w);
    uint2 u; u.x = *(unsigned*)&h0; u.y = *(unsigned*)&h1;
    *(uint2*)(g_Wh + i) = u;
}

/* ================= LayerNorm: one block per token, half out ================= */
__global__ void ln_kernel(const float* __restrict__ x,
                          const float* __restrict__ gamma,
                          const float* __restrict__ beta) {
    int row = blockIdx.x;
    const float* xr = x + (size_t)row * CH;
    __half*      orow = g_xnh + (size_t)row * CH;
    int t = threadIdx.x;

    float v0 = xr[t], v1 = xr[t + 256], v2 = xr[t + 512];
    float s  = v0 + v1 + v2;
    float sq = v0 * v0 + v1 * v1 + v2 * v2;

    __shared__ float redS[8], redQ[8], stats[2];
    #pragma unroll
    for (int o = 16; o; o >>= 1) {
        s  += __shfl_down_sync(0xffffffffu, s,  o);
        sq += __shfl_down_sync(0xffffffffu, sq, o);
    }
    int w = t >> 5, l = t & 31;
    if (l == 0) { redS[w] = s; redQ[w] = sq; }
    __syncthreads();
    if (t == 0) {
        float S = 0.f, Q = 0.f;
        #pragma unroll
        for (int i = 0; i < 8; i++) { S += redS[i]; Q += redQ[i]; }
        float mu  = S * (1.0f / CH);
        float var = Q * (1.0f / CH) - mu * mu;
        stats[0] = mu;
        stats[1] = rsqrtf(var + LN_EPS);
    }
    __syncthreads();
    float mu = stats[0], rs = stats[1];
    orow[t]       = __float2half_rn((v0 - mu) * rs * gamma[t]       + beta[t]);
    orow[t + 256] = __float2half_rn((v1 - mu) * rs * gamma[t + 256] + beta[t + 256]);
    orow[t + 512] = __float2half_rn((v2 - mu) * rs * gamma[t + 512] + beta[t + 512]);
}

/* ===== fp16 128x128 GEMM compute step (8 warps, warp 32x64) ===== */
#define COMPUTE128H(AS, BS)                                               \
    {                                                                     \
        unsigned a[2][4];                                                 \
        _Pragma("unroll")                                                 \
        for (int mi = 0; mi < 2; mi++) {                                  \
            a[mi][0] = AS[wm + mi*16 + lr    ][lc];                       \
            a[mi][1] = AS[wm + mi*16 + lr + 8][lc];                       \
            a[mi][2] = AS[wm + mi*16 + lr    ][lc + 4];                   \
            a[mi][3] = AS[wm + mi*16 + lr + 8][lc + 4];                   \
        }                                                                 \
        _Pragma("unroll")                                                 \
        for (int ni = 0; ni < 8; ni++) {                                  \
            unsigned b0 = BS[wn + ni*8 + lr][lc];                         \
            unsigned b1 = BS[wn + ni*8 + lr][lc + 4];                     \
            _Pragma("unroll")                                             \
            for (int mi = 0; mi < 2; mi++)                                \
                mma16(acc[mi][ni], a[mi], b0, b1);                        \
        }                                                                 \
    }

#define STAGE_U4(ARR, ROWI, U4OFF, v4)                                    \
    ARR[ROWI][U4OFF + 0] = v4.x; ARR[ROWI][U4OFF + 1] = v4.y;             \
    ARR[ROWI][U4OFF + 2] = v4.z; ARR[ROWI][U4OFF + 3] = v4.w;

/* ========== QKV GEMM (fp16 MMA, 128x128, double-buffered) ========== */
__global__ __launch_bounds__(256) void qkv_gemm(const float* __restrict__ bias) {
    __shared__ unsigned As[2][128][10];
    __shared__ unsigned Bs[2][128][10];
    int m0 = blockIdx.y * 128, n0 = blockIdx.x * 128;
    int t = threadIdx.x;
    int warp = t >> 5, lane = t & 31, lr = lane >> 2, lc = lane & 3;
    int wm = (warp >> 1) * 32, wn = (warp & 1) * 64;
    int sr = t >> 1, so = (t & 1) * 4;
    int sh = (t & 1) * 8;

    const __half* A0 = g_xnh + (size_t)(m0 + sr) * CH + sh;
    const __half* B0 = g_Wh  + (size_t)(n0 + sr) * CH + sh;

    float acc[2][8][4] = {};
    {
        uint4 av = *(const uint4*)A0;
        uint4 bv = *(const uint4*)B0;
        STAGE_U4(As[0], sr, so, av)
        STAGE_U4(Bs[0], sr, so, bv)
    }
    __syncthreads();

    const int NT = CH / 16;
    int buf = 0;
    for (int kt = 0; kt < NT; kt++) {
        uint4 nav, nbv;
        bool nxt = (kt + 1) < NT;
        if (nxt) {
            int k0 = (kt + 1) * 16;
            nav = *(const uint4*)(A0 + k0);
            nbv = *(const uint4*)(B0 + k0);
        }
        COMPUTE128H(As[buf], Bs[buf])
        if (nxt) {
            int nb = buf ^ 1;
            STAGE_U4(As[nb], sr, so, nav)
            STAGE_U4(Bs[nb], sr, so, nbv)
        }
        __syncthreads();
        buf ^= 1;
    }
    #pragma unroll
    for (int mi = 0; mi < 2; mi++)
        #pragma unroll
        for (int ni = 0; ni < 8; ni++) {
            int row = m0 + wm + mi*16 + lr;
            int col = n0 + wn + ni*8 + lc*2;
            float b0 = bias[col], b1 = bias[col + 1];
            __half2 h0 = __floats2half2_rn(acc[mi][ni][0] + b0, acc[mi][ni][1] + b1);
            __half2 h1 = __floats2half2_rn(acc[mi][ni][2] + b0, acc[mi][ni][3] + b1);
            *(unsigned*)(g_qkvh + (size_t)row * QKVC + col)     = *(unsigned*)&h0;
            *(unsigned*)(g_qkvh + (size_t)(row+8) * QKVC + col) = *(unsigned*)&h1;
        }
}

/* ========== Scores (fp16 MMA, 128x128, full-K staged, 1 sync) ========== */
__global__ __launch_bounds__(256) void score_gemm() {
    int bh = blockIdx.z, b = bh / NH, h = bh % NH;
    const __half* Q = g_qkvh + (size_t)b * SEQ * QKVC + h * HD;
    const __half* K = g_qkvh + (size_t)b * SEQ * QKVC + CH + h * HD;
    float* S = g_S + (size_t)bh * SEQ * SEQ;

    __shared__ unsigned As[4][128][10];
    __shared__ unsigned Bs[4][128][10];
    int m0 = blockIdx.y * 128, n0 = blockIdx.x * 128;
    int t = threadIdx.x;
    int warp = t >> 5, lane = t & 31, lr = lane >> 2, lc = lane & 3;
    int wm = (warp >> 1) * 32, wn = (warp & 1) * 64;
    int sr = t >> 1, so = (t & 1) * 4, sh = (t & 1) * 8;

    const __half* A0 = Q + (size_t)(m0 + sr) * QKVC + sh;
    const __half* B0 = K + (size_t)(n0 + sr) * QKVC + sh;

    /* stage all K=64 (4 k16 tiles) up front */
    #pragma unroll
    for (int kt = 0; kt < 4; kt++) {
        uint4 av = *(const uint4*)(A0 + kt * 16);
        uint4 bv = *(const uint4*)(B0 + kt * 16);
        STAGE_U4(As[kt], sr, so, av)
        STAGE_U4(Bs[kt], sr, so, bv)
    }
    __syncthreads();

    float acc[2][8][4] = {};
    #pragma unroll
    for (int kt = 0; kt < 4; kt++) {
        COMPUTE128H(As[kt], Bs[kt])
    }

    #pragma unroll
    for (int mi = 0; mi < 2; mi++)
        #pragma unroll
        for (int ni = 0; ni < 8; ni++) {
            int row = m0 + wm + mi*16 + lr;
            int col = n0 + wn + ni*8 + lc*2;
            float2 v0 = make_float2(acc[mi][ni][0] * SCALE, acc[mi][ni][1] * SCALE);
            float2 v1 = make_float2(acc[mi][ni][2] * SCALE, acc[mi][ni][3] * SCALE);
            *(float2*)(S + (size_t)row * SEQ + col)     = v0;
            *(float2*)(S + (size_t)(row+8) * SEQ + col) = v1;
        }
}

/* ============ Lateral inhibition conv + row softmax (fp16 out) ============ */
#define CR 4
__global__ __launch_bounds__(256) void conv_softmax_v2() {
    int bh = blockIdx.y;
    int i0 = blockIdx.x * CR;
    const float* S = g_S + (size_t)bh * SEQ * SEQ;
    __half*      P = g_Ph + (size_t)bh * SEQ * SEQ;

    __shared__ float rows[6][SEQ];
    __shared__ float red[CR][8];
    __shared__ float bc[CR];

    int t = threadIdx.x, lane = t & 31, w = t >> 5;
    int j0 = t * 4;

    #pragma unroll
    for (int r = 0; r < 6; r++) {
        int gi = i0 - 1 + r;
        float4 v = make_float4(0.f, 0.f, 0.f, 0.f);
        if (gi >= 0 && gi < SEQ) v = *(const float4*)(S + (size_t)gi * SEQ + j0);
        *(float4*)&rows[r][j0] = v;
    }
    __syncthreads();

    float a[CR][4], mx[CR];
    #pragma unroll
    for (int r = 0; r < CR; r++) {
        float4 x = *(const float4*)&rows[r    ][j0];
        float4 y = *(const float4*)&rows[r + 1][j0];
        float4 z = *(const float4*)&rows[r + 2][j0];
        float4 vs;
        vs.x = x.x + y.x + z.x;  vs.y = x.y + y.y + z.y;
        vs.z = x.z + y.z + z.z;  vs.w = x.w + y.w + z.w;

        float left  = __shfl_up_sync(0xffffffffu, vs.w, 1);
        float right = __shfl_down_sync(0xffffffffu, vs.x, 1);
        if (lane == 0) {
            int j = j0 - 1;
            left = (j >= 0) ? rows[r][j] + rows[r + 1][j] + rows[r + 2][j] : 0.f;
        }
        if (lane == 31) {
            int j = j0 + 4;
            right = (j < SEQ) ? rows[r][j] + rows[r + 1][j] + rows[r + 2][j] : 0.f;
        }

        a[r][0] = (1.0f + BETA) * y.x - BETA * (left + vs.x + vs.y);
        a[r][1] = (1.0f + BETA) * y.y - BETA * (vs.x + vs.y + vs.z);
        a[r][2] = (1.0f + BETA) * y.z - BETA * (vs.y + vs.z + vs.w);
        a[r][3] = (1.0f + BETA) * y.w - BETA * (vs.z + vs.w + right);
        mx[r] = fmaxf(fmaxf(a[r][0], a[r][1]), fmaxf(a[r][2], a[r][3]));
    }

    #pragma unroll
    for (int r = 0; r < CR; r++) {
        float m = mx[r];
        #pragma unroll
        for (int o = 16; o; o >>= 1) m = fmaxf(m, __shfl_xor_sync(0xffffffffu, m, o));
        if (lane == 0) red[r][w] = m;
    }
    __syncthreads();
    if (t < CR) {
        float m = red[t][0];
        #pragma unroll
        for (int k = 1; k < 8; k++) m = fmaxf(m, red[t][k]);
        bc[t] = m;
    }
    __syncthreads();

    float sm[CR];
    #pragma unroll
    for (int r = 0; r < CR; r++) {
        float M = bc[r];
        float s = 0.f;
        #pragma unroll
        for (int q = 0; q < 4; q++) { a[r][q] = __expf(a[r][q] - M); s += a[r][q]; }
        sm[r] = s;
    }
    __syncthreads();
    #pragma unroll
    for (int r = 0; r < CR; r++) {
        float s = sm[r];
        #pragma unroll
        for (int o = 16; o; o >>= 1) s += __shfl_xor_sync(0xffffffffu, s, o);
        if (lane == 0) red[r][w] = s;
    }
    __syncthreads();
    if (t < CR) {
        float s = 0.f;
        #pragma unroll
        for (int k = 0; k < 8; k++) s += red[t][k];
        bc[t] = 1.0f / s;
    }
    __syncthreads();

    #pragma unroll
    for (int r = 0; r < CR; r++) {
        float inv = bc[r];
        __half2 h01 = __floats2half2_rn(a[r][0] * inv, a[r][1] * inv);
        __half2 h23 = __floats2half2_rn(a[r][2] * inv, a[r][3] * inv);
        uint2 u;
        u.x = *(unsigned*)&h01;
        u.y = *(unsigned*)&h23;
        *(uint2*)(P + (size_t)(i0 + r) * SEQ + j0) = u;
    }
}

/* ========== PV GEMM (fp16 MMA, double-buffered): out = P @ V ========== */
__global__ __launch_bounds__(256) void pv_gemm(float* __restrict__ out) {
    int bh = blockIdx.y, b = bh / NH, h = bh % NH;
    const __half* Pg = g_Ph + (size_t)bh * SEQ * SEQ;
    const __half* Vh = g_qkvh + (size_t)b * SEQ * QKVC + 2 * CH + h * HD;
    int m0 = blockIdx.x * 128;

    __shared__ unsigned Ps[2][128][10];
    __shared__ unsigned Vsu[2][64][10];

    int t = threadIdx.x;
    int warp = t >> 5, lane = t & 31, lr = lane >> 2, lc = lane & 3;
    int wm = (warp >> 1) * 32, wn = (warp & 1) * 32;
    int pr = t >> 1, ph = (t & 1) * 4, phh = (t & 1) * 8;
    int kp = (t & 127) >> 4, n4 = t & 15;

    const __half* Prow = Pg + (size_t)(m0 + pr) * SEQ + phh;

    float acc[2][4][4] = {};

    /* prologue: stage k-tile 0 into buf 0 */
    {
        uint4 pv4 = *(const uint4*)Prow;
        STAGE_U4(Ps[0], pr, ph, pv4)
        if (t < 128) {
            uint2 lo = *(const uint2*)(Vh + (size_t)(2*kp    ) * QKVC + n4 * 4);
            uint2 hi = *(const uint2*)(Vh + (size_t)(2*kp + 1) * QKVC + n4 * 4);
            const __half* lp = (const __half*)&lo;
            const __half* hp = (const __half*)&hi;
            #pragma unroll
            for (int i = 0; i < 4; i++) {
                __half2 pk = __halves2half2(lp[i], hp[i]);
                Vsu[0][n4*4 + i][kp] = *(unsigned*)&pk;
            }
        }
    }
    __syncthreads();

    const int NT = SEQ / 16;
    int buf = 0;
    for (int kt = 0; kt < NT; kt++) {
        uint4 npv; uint2 nlo, nhi;
        bool nxt = (kt + 1) < NT;
        if (nxt) {
            int k0 = (kt + 1) * 16;
            npv = *(const uint4*)(Prow + k0);
            if (t < 128) {
                nlo = *(const uint2*)(Vh + (size_t)(k0 + 2*kp    ) * QKVC + n4 * 4);
                nhi = *(const uint2*)(Vh + (size_t)(k0 + 2*kp + 1) * QKVC + n4 * 4);
            }
        }

        /* compute from buf */
        unsigned a[2][4];
        #pragma unroll
        for (int mi = 0; mi < 2; mi++) {
            a[mi][0] = Ps[buf][wm + mi*16 + lr    ][lc];
            a[mi][1] = Ps[buf][wm + mi*16 + lr + 8][lc];
            a[mi][2] = Ps[buf][wm + mi*16 + lr    ][lc + 4];
            a[mi][3] = Ps[buf][wm + mi*16 + lr + 8][lc + 4];
        }
        #pragma unroll
        for (int ni = 0; ni < 4; ni++) {
            unsigned b0 = Vsu[buf][wn + ni*8 + lr][lc];
            unsigned b1 = Vsu[buf][wn + ni*8 + lr][lc + 4];
            #pragma unroll
            for (int mi = 0; mi < 2; mi++)
                mma16(acc[mi][ni], a[mi], b0, b1);
        }

        if (nxt) {
            int nb = buf ^ 1;
            STAGE_U4(Ps[nb], pr, ph, npv)
            if (t < 128) {
                const __half* lp = (const __half*)&nlo;
                const __half* hp = (const __half*)&nhi;
                #pragma unroll
                for (int i = 0; i < 4; i++) {
                    __half2 pk = __halves2half2(lp[i], hp[i]);
                    Vsu[nb][n4*4 + i][kp] = *(unsigned*)&pk;
                }
            }
        }
        __syncthreads();
        buf ^= 1;
    }

    #pragma unroll
    for (int mi = 0; mi < 2; mi++)
        #pragma unroll
        for (int ni = 0; ni < 4; ni++) {
            int row = m0 + wm + mi*16 + lr;
            int col = wn + ni*8 + lc*2;
            out[((size_t)b * SEQ + row) * CH + h*HD + col    ] = acc[mi][ni][0];
            out[((size_t)b * SEQ + row) * CH + h*HD + col + 1] = acc[mi][ni][1];
            out[((size_t)b * SEQ + row + 8) * CH + h*HD + col    ] = acc[mi][ni][2];
            out[((size_t)b * SEQ + row + 8) * CH + h*HD + col + 1] = acc[mi][ni][3];
        }
}

extern "C" void kernel_launch(void* const* d_in, const int* in_sizes, int n_in,
                              void* d_out, int out_size) {
    const float* x     = (const float*)d_in[0];
    const float* qkv_w = (const float*)d_in[1];
    const float* qkv_b = (const float*)d_in[2];
    const float* ln_g  = (const float*)d_in[3];
    const float* ln_b  = (const float*)d_in[4];
    float* out = (float*)d_out;

    wcvt_kernel<<<(QKVC * CH) / (256 * 4), 256>>>(qkv_w);
    ln_kernel<<<ROWS, 256>>>(x, ln_g, ln_b);
    qkv_gemm<<<dim3(QKVC / 128, ROWS / 128), 256>>>(qkv_b);
    score_gemm<<<dim3(SEQ / 128, SEQ / 128, BH), 256>>>();
    conv_softmax_v2<<<dim3(SEQ / CR, BH), 256>>>();
    pv_gemm<<<dim3(SEQ / 128, BH), 256>>>(out);
}